// round 1
// baseline (speedup 1.0000x reference)
#include <cuda_runtime.h>
#include <cstdint>

#define T_TOK 8192
#define IN_F  2048
#define OUT_F 2048
#define THRESH 6.0f

// ---------------- device scratch (no allocations allowed) ----------------
__device__ int8_t   g_wq[(size_t)OUT_F * IN_F];   // 4 MB
__device__ float    g_wscale[OUT_F];              // w_absmax/127
__device__ int8_t   g_xq[(size_t)T_TOK * IN_F];   // 16 MB
__device__ float    g_xscale[T_TOK];              // x_absmax/127
__device__ unsigned g_colmax[IN_F];               // float bits (nonneg)
__device__ int      g_outidx[IN_F];
__device__ int      g_nout;

// ---------------- init: zero colmax ----------------
__global__ void k_init() {
    int i = blockIdx.x * 256 + threadIdx.x;
    if (i < IN_F) g_colmax[i] = 0u;
    if (i == 0) g_nout = 0;
}

// ---------------- column absmax over all tokens ----------------
__global__ void k_colmax(const float* __restrict__ x) {
    int c = blockIdx.x * 256 + threadIdx.x;
    const float* p = x + (size_t)blockIdx.y * 256 * IN_F + c;
    float m = 0.f;
#pragma unroll 4
    for (int r = 0; r < 256; ++r) m = fmaxf(m, fabsf(p[(size_t)r * IN_F]));
    atomicMax(&g_colmax[c], __float_as_uint(m));
}

// ---------------- block max reduction helper (256 threads) ----------------
__device__ __forceinline__ float block_reduce_max(float v, float* sh) {
#pragma unroll
    for (int o = 16; o > 0; o >>= 1) v = fmaxf(v, __shfl_xor_sync(0xffffffffu, v, o));
    int w = threadIdx.x >> 5;
    if ((threadIdx.x & 31) == 0) sh[w] = v;
    __syncthreads();
    float r = sh[0];
#pragma unroll
    for (int i = 1; i < 8; ++i) r = fmaxf(r, sh[i]);
    return r;
}

// ---------------- weight quantization: one block per output row ----------------
__global__ void k_quantw(const float* __restrict__ w) {
    __shared__ float sh[8];
    int row = blockIdx.x;
    const float* wr = w + (size_t)row * IN_F;
    float v[8]; float m = 0.f;
#pragma unroll
    for (int i = 0; i < 8; ++i) {
        v[i] = wr[threadIdx.x + i * 256];
        m = fmaxf(m, fabsf(v[i]));
    }
    float amax = fmaxf(block_reduce_max(m, sh), 1e-6f);
    float s = 127.0f / amax;
#pragma unroll
    for (int i = 0; i < 8; ++i) {
        float q = rintf(v[i] * s);
        q = fminf(fmaxf(q, -127.f), 127.f);
        g_wq[(size_t)row * IN_F + threadIdx.x + i * 256] = (int8_t)q;
    }
    if (threadIdx.x == 0) g_wscale[row] = amax / 127.0f;
}

// ---------------- deterministic ordered gather of outlier columns ----------------
__global__ void k_gather() {
    __shared__ int warp_cnt[8];
    __shared__ int base_s;
    int tid = threadIdx.x;
    int lane = tid & 31, w = tid >> 5;
    if (tid == 0) base_s = 0;
    __syncthreads();
    for (int start = 0; start < IN_F; start += 256) {
        int c = start + tid;
        bool f = __uint_as_float(g_colmax[c]) > THRESH;
        unsigned msk = __ballot_sync(0xffffffffu, f);
        if (lane == 0) warp_cnt[w] = __popc(msk);
        __syncthreads();
        int prefix = base_s;
        for (int i = 0; i < w; ++i) prefix += warp_cnt[i];
        if (f) g_outidx[prefix + __popc(msk & ((1u << lane) - 1u))] = c;
        __syncthreads();
        if (tid == 0) {
            int tot = 0;
            for (int i = 0; i < 8; ++i) tot += warp_cnt[i];
            base_s += tot;
        }
        __syncthreads();
    }
    if (tid == 0) g_nout = base_s;
}

// ---------------- activation quantization: one block per token ----------------
__global__ void k_quantx(const float* __restrict__ x) {
    __shared__ float sh[8];
    int t = blockIdx.x;
    const float* xr = x + (size_t)t * IN_F;
    float v[8]; float m = 0.f;
#pragma unroll
    for (int i = 0; i < 8; ++i) {
        int c = threadIdx.x + i * 256;
        float f = xr[c];
        if (__uint_as_float(g_colmax[c]) > THRESH) f = 0.f;   // outlier col -> fp path
        v[i] = f;
        m = fmaxf(m, fabsf(f));
    }
    float amax = fmaxf(block_reduce_max(m, sh), 1e-6f);
    float s = 127.0f / amax;
#pragma unroll
    for (int i = 0; i < 8; ++i) {
        float q = rintf(v[i] * s);
        q = fminf(fmaxf(q, -127.f), 127.f);
        g_xq[(size_t)t * IN_F + threadIdx.x + i * 256] = (int8_t)q;
    }
    if (threadIdx.x == 0) g_xscale[t] = amax / 127.0f;
}

// ---------------- int8 DP4A GEMM + fused outlier fp + dequant epilogue ----------------
// BM=BN=128, BK=64 int8 (= 16 int32 = 4 int4 per row per tile), 256 threads, 8x8 microtile.
#define BM 128
#define BN 128
#define KTILES (IN_F / 64)   // 32

__global__ __launch_bounds__(256) void k_gemm(const float* __restrict__ x,
                                              const float* __restrict__ bias,
                                              float* __restrict__ out) {
    // A/B buffers padded: 5 int4 per row (20 int32) to kill bank conflicts on LDS.128
    __shared__ union {
        struct { int4 A[2][BM * 5]; int4 B[2][BN * 5]; } g;     // 40 KB
        struct { float xo[BM * 17]; float wo[BN * 17]; } e;     // ~17 KB (reused in epilogue)
    } smem;

    const int tid = threadIdx.x;
    const int tx = tid & 15;          // n dir: cols tx + j*16
    const int ty = tid >> 4;          // m dir: rows ty*8 + i
    const int m_blk = blockIdx.y * BM;
    const int n_blk = blockIdx.x * BN;

    // global loader mapping: each thread handles (row=lrow, q=lq) and (row=lrow+64, q=lq)
    const int lrow = tid >> 2;        // 0..63
    const int lq   = tid & 3;         // 0..3 int4 within 64B k-slab

    const int4* gA = reinterpret_cast<const int4*>(g_xq);  // row pitch 128 int4
    const int4* gB = reinterpret_cast<const int4*>(g_wq);

    int acc[8][8];
#pragma unroll
    for (int i = 0; i < 8; ++i)
#pragma unroll
        for (int j = 0; j < 8; ++j) acc[i][j] = 0;

    // preload tile 0
    int4 pa0 = gA[(size_t)(m_blk + lrow) * 128 + lq];
    int4 pa1 = gA[(size_t)(m_blk + lrow + 64) * 128 + lq];
    int4 pb0 = gB[(size_t)(n_blk + lrow) * 128 + lq];
    int4 pb1 = gB[(size_t)(n_blk + lrow + 64) * 128 + lq];
    smem.g.A[0][lrow * 5 + lq] = pa0;
    smem.g.A[0][(lrow + 64) * 5 + lq] = pa1;
    smem.g.B[0][lrow * 5 + lq] = pb0;
    smem.g.B[0][(lrow + 64) * 5 + lq] = pb1;

#pragma unroll 1
    for (int t = 0; t < KTILES; ++t) {
        __syncthreads();
        const int buf = t & 1;
        const bool more = (t + 1) < KTILES;
        if (more) {
            int off = (t + 1) * 4 + lq;
            pa0 = gA[(size_t)(m_blk + lrow) * 128 + off];
            pa1 = gA[(size_t)(m_blk + lrow + 64) * 128 + off];
            pb0 = gB[(size_t)(n_blk + lrow) * 128 + off];
            pb1 = gB[(size_t)(n_blk + lrow + 64) * 128 + off];
        }
#pragma unroll
        for (int kk = 0; kk < 4; ++kk) {
            int4 af[8], bf[8];
#pragma unroll
            for (int i = 0; i < 8; ++i) af[i] = smem.g.A[buf][(ty * 8 + i) * 5 + kk];
#pragma unroll
            for (int j = 0; j < 8; ++j) bf[j] = smem.g.B[buf][(tx + j * 16) * 5 + kk];
#pragma unroll
            for (int i = 0; i < 8; ++i)
#pragma unroll
                for (int j = 0; j < 8; ++j) {
                    acc[i][j] = __dp4a(af[i].x, bf[j].x, acc[i][j]);
                    acc[i][j] = __dp4a(af[i].y, bf[j].y, acc[i][j]);
                    acc[i][j] = __dp4a(af[i].z, bf[j].z, acc[i][j]);
                    acc[i][j] = __dp4a(af[i].w, bf[j].w, acc[i][j]);
                }
        }
        if (more) {
            const int nb = buf ^ 1;
            smem.g.A[nb][lrow * 5 + lq] = pa0;
            smem.g.A[nb][(lrow + 64) * 5 + lq] = pa1;
            smem.g.B[nb][lrow * 5 + lq] = pb0;
            smem.g.B[nb][(lrow + 64) * 5 + lq] = pb1;
        }
    }

    // ---- dequant + fp outlier epilogue ----
    float xs[8], ws[8], bs[8];
#pragma unroll
    for (int i = 0; i < 8; ++i) xs[i] = g_xscale[m_blk + ty * 8 + i];
#pragma unroll
    for (int j = 0; j < 8; ++j) {
        int gn = n_blk + tx + j * 16;
        ws[j] = g_wscale[gn];
        bs[j] = bias[gn];
    }

    float facc[8][8];
#pragma unroll
    for (int i = 0; i < 8; ++i)
#pragma unroll
        for (int j = 0; j < 8; ++j) facc[i][j] = xs[i] * (float)acc[i][j];

    const int nout = g_nout;
    for (int base = 0; base < nout; base += 16) {
        __syncthreads();   // safe to reuse smem: all GEMM reads finished
        const int rem = nout - base;
        for (int i = tid; i < BM * 16; i += 256) {
            int r = i >> 4, c = i & 15;
            float xv = 0.f, wv = 0.f;
            if (c < rem) {
                int col = g_outidx[base + c];
                xv = x[(size_t)(m_blk + r) * IN_F + col];
                wv = (float)g_wq[(size_t)(n_blk + r) * IN_F + col];
            }
            smem.e.xo[r * 17 + c] = xv;
            smem.e.wo[r * 17 + c] = wv;
        }
        __syncthreads();
#pragma unroll
        for (int c = 0; c < 16; ++c) {
            float xa[8], wb[8];
#pragma unroll
            for (int i = 0; i < 8; ++i) xa[i] = smem.e.xo[(ty * 8 + i) * 17 + c];
#pragma unroll
            for (int j = 0; j < 8; ++j) wb[j] = smem.e.wo[(tx + j * 16) * 17 + c];
#pragma unroll
            for (int i = 0; i < 8; ++i)
#pragma unroll
                for (int j = 0; j < 8; ++j) facc[i][j] += xa[i] * wb[j];
        }
    }

#pragma unroll
    for (int i = 0; i < 8; ++i) {
        size_t gm = m_blk + ty * 8 + i;
#pragma unroll
        for (int j = 0; j < 8; ++j) {
            int gn = n_blk + tx + j * 16;
            out[gm * OUT_F + gn] = ws[j] * facc[i][j] + bs[j];
        }
    }
}

// ---------------- launch ----------------
extern "C" void kernel_launch(void* const* d_in, const int* in_sizes, int n_in,
                              void* d_out, int out_size) {
    const float* x    = (const float*)d_in[0];   // [2,4096,2048]
    const float* w    = (const float*)d_in[1];   // [2048,2048]
    const float* bias = (const float*)d_in[2];   // [2048]
    float* out = (float*)d_out;                  // [2,4096,2048]

    k_init<<<8, 256>>>();
    k_colmax<<<dim3(IN_F / 256, 32), 256>>>(x);
    k_quantw<<<OUT_F, 256>>>(w);
    k_gather<<<1, 256>>>();
    k_quantx<<<T_TOK, 256>>>(x);
    k_gemm<<<dim3(OUT_F / BN, T_TOK / BM), 256>>>(x, bias, out);
}